// round 7
// baseline (speedup 1.0000x reference)
#include <cuda_runtime.h>
#include <cstdint>

// Problem constants (fixed by the reference).
#define BB   4
#define DD   128
#define HH   128
#define WW   128
#define NMAX 500000
#define CIN  32
#define COUT 32
#define GRID_SZ (BB * DD * HH * WW)   // 8,388,608
#define EPSV 1e-4f
#define FULLMASK 0xffffffffu
#define CAP    40960                  // per-offset pair capacity (expected ~30k)
#define O_SELF 62                     // (dz,dy,dx) = (0,0,0)

// -------- device scratch (allocation-free: static __device__ globals) --------
__device__ int   g_grid[GRID_SZ];                 // flat voxel -> site row (-1)
__device__ int   g_flat[NMAX];                    // packed flat index per site
__device__ float g_feat[(size_t)(NMAX + 1) * CIN];// normalized feats + zero row
__device__ float g_stats[2 * CIN];
__device__ float g_scale[CIN];
__device__ float g_bias[CIN];
__device__ int2  g_pairs[125 * CAP];              // per-offset (site, nbr) lists
__device__ int   g_cnt[125];

// f32x2 packed FMA (FFMA2) — PTX only.
#define FFMA2(acc, f2, w2) \
    asm("fma.rn.f32x2 %0, %1, %2, %3;" : "=l"(acc) : "l"(f2), "l"(w2), "l"(acc))

// -------- kernel 1: reset grid to -1, zero counters/stats/zero-row ----------
__global__ void k_reset() {
    int i = blockIdx.x * blockDim.x + threadIdx.x;
    int stride = gridDim.x * blockDim.x;
    int4 m1 = make_int4(-1, -1, -1, -1);
    for (int e = i; e < GRID_SZ / 4; e += stride)
        reinterpret_cast<int4*>(g_grid)[e] = m1;
    if (blockIdx.x == 0) {
        if (threadIdx.x < 2 * CIN) g_stats[threadIdx.x] = 0.f;
        if (threadIdx.x < 125)     g_cnt[threadIdx.x] = 0;
        if (threadIdx.x < CIN)     g_feat[(size_t)NMAX * CIN + threadIdx.x] = 0.f;
    }
}

// -------- kernel 2: scatter site rows into the grid, pack coords ------------
__global__ void k_scatter(const int* __restrict__ coords, int Nv) {
    int i = blockIdx.x * blockDim.x + threadIdx.x;
    if (i < Nv) {
        int4 c = reinterpret_cast<const int4*>(coords)[i];  // b, z, y, x
        int fl = (((c.x * DD + c.y) * HH + c.z) * WW) + c.w;
        g_grid[fl] = i;
        g_flat[i] = fl;
    }
}

// -------- kernel 3: per-channel sum / sumsq ---------------------------------
__global__ void k_stats(const float* __restrict__ x, int Nv) {
    __shared__ float ss[8][33];
    __shared__ float ss2[8][33];
    int tid = threadIdx.x;
    int c = tid & 31;
    int wid = tid >> 5;
    float s = 0.f, s2 = 0.f;
    int total = Nv * CIN;
    int stride = gridDim.x * blockDim.x;  // multiple of 32 -> channel fixed
    for (int e = blockIdx.x * blockDim.x + tid; e < total; e += stride) {
        float v = x[e];
        s += v;
        s2 += v * v;
    }
    ss[wid][c] = s;
    ss2[wid][c] = s2;
    __syncthreads();
    if (tid < 32) {
        float a = 0.f, b = 0.f;
#pragma unroll
        for (int k = 0; k < 8; k++) { a += ss[k][tid]; b += ss2[k][tid]; }
        atomicAdd(&g_stats[tid], a);
        atomicAdd(&g_stats[32 + tid], b);
    }
}

// -------- kernel 4: fold BN into per-channel scale/bias ---------------------
__global__ void k_finalize(const float* __restrict__ gamma,
                           const float* __restrict__ beta, int Nv) {
    int c = threadIdx.x;
    if (c < CIN) {
        float invN = 1.0f / (float)Nv;
        float mean = g_stats[c] * invN;
        float var = g_stats[32 + c] * invN - mean * mean;
        float sc = gamma[c] * rsqrtf(var + EPSV);
        g_scale[c] = sc;
        g_bias[c] = beta[c] - mean * sc;
    }
}

// -------- kernel 5: y = relu(x*scale + bias) --------------------------------
__global__ void k_norm(const float* __restrict__ x, int Nv) {
    int e = blockIdx.x * blockDim.x + threadIdx.x;  // float4 units
    int total = Nv * (CIN / 4);
    if (e < total) {
        float4 v = reinterpret_cast<const float4*>(x)[e];
        int c0 = (e * 4) & 31;
        float4 r;
        r.x = fmaxf(fmaf(v.x, g_scale[c0 + 0], g_bias[c0 + 0]), 0.f);
        r.y = fmaxf(fmaf(v.y, g_scale[c0 + 1], g_bias[c0 + 1]), 0.f);
        r.z = fmaxf(fmaf(v.z, g_scale[c0 + 2], g_bias[c0 + 2]), 0.f);
        r.w = fmaxf(fmaf(v.w, g_scale[c0 + 3], g_bias[c0 + 3]), 0.f);
        reinterpret_cast<float4*>(g_feat)[e] = r;
    }
}

// -------- kernel 6: rulebook build. blockIdx.y = (dz,dy); dx window merged --
__global__ void __launch_bounds__(256) k_build(int Nv) {
    const int dzdy = blockIdx.y;                 // 0..24
    const int dz = dzdy / 5 - 2;
    const int dy = dzdy % 5 - 2;
    const int lane = threadIdx.x & 31;
    int site = blockIdx.x * blockDim.x + threadIdx.x;

    int nb[5];
#pragma unroll
    for (int i = 0; i < 5; i++) nb[i] = -1;

    if (site < Nv) {
        int fl = g_flat[site];
        int z = (fl >> 14) & 127, y = (fl >> 7) & 127, x = fl & 127;
        if (((unsigned)(z + dz) < 128u) & ((unsigned)(y + dy) < 128u)) {
            int nbase = fl + dz * (HH * WW) + dy * WW;
#pragma unroll
            for (int i = 0; i < 5; i++) {
                int nx = x + i - 2;
                if ((unsigned)nx < 128u) nb[i] = g_grid[nbase + i - 2];
            }
        }
    }

#pragma unroll
    for (int i = 0; i < 5; i++) {
        int o = dzdy * 5 + i;
        if (o == O_SELF) continue;               // self handled densely
        bool v = nb[i] >= 0;
        unsigned m = __ballot_sync(FULLMASK, v);
        if (!m) continue;
        int leader = __ffs(m) - 1;
        int base = 0;
        if (lane == leader) base = atomicAdd(&g_cnt[o], __popc(m));
        base = __shfl_sync(FULLMASK, base, leader);
        if (v) {
            int pos = base + __popc(m & ((1u << lane) - 1u));
            if (pos < CAP) g_pairs[o * CAP + pos] = make_int2(site, nb[i]);
        }
    }
}

// -------- kernel 7: pad each offset list to a multiple of 32 ----------------
__global__ void k_pad() {
    int o = blockIdx.x;
    if (o == O_SELF) return;
    int c = min(g_cnt[o], CAP);
    __syncthreads();
    int padded = min((c + 31) & ~31, CAP);
    for (int t = c + (int)threadIdx.x; t < padded; t += blockDim.x)
        g_pairs[o * CAP + t] = make_int2(0, NMAX);  // zero feature row -> +0
    if (threadIdx.x == 0) g_cnt[o] = padded;
}

// -------- kernel 8: self offset (always valid), plain coalesced stores ------
// Writes every out row -> also serves as out initialization.
__global__ void __launch_bounds__(256) k_self(const float* __restrict__ weight,
                                              float* __restrict__ out, int Nv) {
    const int lane = threadIdx.x & 31;
    unsigned long long w[16];
    const float* wp = weight + O_SELF * (CIN * COUT) + lane;
#pragma unroll
    for (int c = 0; c < 16; c++) {
        float a = __ldg(wp + (2 * c) * COUT);
        float b = __ldg(wp + (2 * c + 1) * COUT);
        asm("mov.b64 %0, {%1, %2};" : "=l"(w[c]) : "f"(a), "f"(b));
    }
    int nwarps = gridDim.x * (blockDim.x >> 5);
    int wid = (blockIdx.x * blockDim.x + threadIdx.x) >> 5;
    for (int base = wid * 32; base < Nv; base += nwarps * 32) {
        int mcount = min(32, Nv - base);
        for (int j = 0; j < mcount; j++) {
            const ulonglong2* fp = reinterpret_cast<const ulonglong2*>(
                g_feat + (size_t)(base + j) * CIN);
            unsigned long long acc = 0ull;
#pragma unroll
            for (int t = 0; t < 8; t++) {
                ulonglong2 f = fp[t];
                FFMA2(acc, f.x, w[2 * t]);
                FFMA2(acc, f.y, w[2 * t + 1]);
            }
            float lo, hi;
            asm("mov.b64 {%0, %1}, %2;" : "=f"(lo), "=f"(hi) : "l"(acc));
            out[(size_t)(base + j) * COUT + lane] = lo + hi;
        }
    }
}

// -------- kernel 9: pair GEMM. blockIdx.y = offset (o != 62) ----------------
// Register weights per block, dense 32-pair chunks, FFMA2 math, vectorized
// red.v4 scatter (4 pairs share one warp-wide vector reduction).
__global__ void __launch_bounds__(256) k_pair(const float* __restrict__ weight,
                                              float* __restrict__ out) {
    int ob = blockIdx.y;
    int o = ob + (ob >= O_SELF);
    const int lane = threadIdx.x & 31;

    unsigned long long w[16];
    const float* wp = weight + o * (CIN * COUT) + lane;
#pragma unroll
    for (int c = 0; c < 16; c++) {
        float a = __ldg(wp + (2 * c) * COUT);
        float b = __ldg(wp + (2 * c + 1) * COUT);
        asm("mov.b64 %0, {%1, %2};" : "=l"(w[c]) : "f"(a), "f"(b));
    }

    const int nchunk = g_cnt[o] >> 5;            // padded to multiple of 32
    const int nwarps = gridDim.x * (blockDim.x >> 5);
    int wid = (blockIdx.x * blockDim.x + threadIdx.x) >> 5;
    const int p = lane >> 3;                     // pair slot within group of 4
    const int c4 = (lane & 7) * 4;               // cout base for red.v4

    for (int ch = wid; ch < nchunk; ch += nwarps) {
        int2 pr = g_pairs[o * CAP + ch * 32 + lane];  // coalesced
#pragma unroll
        for (int g = 0; g < 8; g++) {
            float a0, a1, a2, a3;
            {
                float aa[4];
#pragma unroll
                for (int q = 0; q < 4; q++) {
                    int n = __shfl_sync(FULLMASK, pr.y, g * 4 + q);
                    const ulonglong2* fp = reinterpret_cast<const ulonglong2*>(
                        g_feat + (size_t)n * CIN);
                    unsigned long long acc = 0ull;
#pragma unroll
                    for (int t = 0; t < 8; t++) {
                        ulonglong2 f = fp[t];
                        FFMA2(acc, f.x, w[2 * t]);
                        FFMA2(acc, f.y, w[2 * t + 1]);
                    }
                    float lo, hi;
                    asm("mov.b64 {%0, %1}, %2;" : "=f"(lo), "=f"(hi) : "l"(acc));
                    aa[q] = lo + hi;
                }
                a0 = aa[0]; a1 = aa[1]; a2 = aa[2]; a3 = aa[3];
            }
            // Transpose: lane takes pair p's couts [c4, c4+4) and issues one
            // 16B vector reduction (4 pairs per warp-instruction).
            float v[4];
#pragma unroll
            for (int q = 0; q < 4; q++) {
                float r0 = __shfl_sync(FULLMASK, a0, c4 + q);
                float r1 = __shfl_sync(FULLMASK, a1, c4 + q);
                float r2 = __shfl_sync(FULLMASK, a2, c4 + q);
                float r3 = __shfl_sync(FULLMASK, a3, c4 + q);
                v[q] = (p == 0) ? r0 : (p == 1) ? r1 : (p == 2) ? r2 : r3;
            }
            int s = __shfl_sync(FULLMASK, pr.x, g * 4 + p);
            float* dst = out + (size_t)s * COUT + c4;
            asm volatile("red.global.add.v4.f32 [%0], {%1, %2, %3, %4};"
                         :: "l"(dst), "f"(v[0]), "f"(v[1]), "f"(v[2]), "f"(v[3])
                         : "memory");
        }
    }
}

// -------- launch ------------------------------------------------------------
extern "C" void kernel_launch(void* const* d_in, const int* in_sizes, int n_in,
                              void* d_out, int out_size) {
    const float* feats  = (const float*)d_in[0];   // [N, 32]
    const int*   coords = (const int*)d_in[1];     // [N, 4]
    const float* gamma  = (const float*)d_in[2];   // [32]
    const float* beta   = (const float*)d_in[3];   // [32]
    const float* weight = (const float*)d_in[4];   // [125, 32, 32]
    float* out = (float*)d_out;                    // [N, 32]

    int Nv = in_sizes[0] / CIN;
    if (Nv > NMAX) Nv = NMAX;

    k_reset<<<2048, 256>>>();
    k_scatter<<<(Nv + 255) / 256, 256>>>(coords, Nv);
    k_stats<<<1024, 256>>>(feats, Nv);
    k_finalize<<<1, 32>>>(gamma, beta, Nv);
    k_norm<<<(Nv * (CIN / 4) + 255) / 256, 256>>>(feats, Nv);

    dim3 gb((Nv + 255) / 256, 25);
    k_build<<<gb, 256>>>(Nv);
    k_pad<<<125, 64>>>();

    k_self<<<512, 256>>>(weight, out, Nv);         // also initializes out
    dim3 gp(16, 124);
    k_pair<<<gp, 256>>>(weight, out);
}

// round 8
// speedup vs baseline: 1.5004x; 1.5004x over previous
#include <cuda_runtime.h>
#include <cstdint>

// Problem constants (fixed by the reference).
#define BB   4
#define DD   128
#define HH   128
#define WW   128
#define NMAX 500000
#define CIN  32
#define COUT 32
#define KVOL 125
#define GRID_SZ (BB * DD * HH * WW)   // 8,388,608
#define EPSV 1e-4f
#define FULLMASK 0xffffffffu
#define SITES_PER_BLOCK 2048          // 256 threads x 8 iterations

// -------- device scratch (allocation-free: static __device__ globals) --------
__device__ int   g_grid[GRID_SZ];          // flat voxel -> site row (-1 inactive)
__device__ int   g_flat[NMAX];             // packed flat index per site
__device__ __align__(16) float g_feat[(size_t)NMAX * CIN]; // normalized feats
__device__ float g_stats[2 * CIN];
__device__ float g_scale[CIN];
__device__ float g_bias[CIN];

// f32x2 packed FMA — PTX only.
#define FFMA2(acc, f2, w2) \
    asm("fma.rn.f32x2 %0, %1, %2, %3;" : "=l"(acc) : "l"(f2), "l"(w2), "l"(acc))

// -------- kernel 1: reset grid to -1, zero out, zero stats ------------------
__global__ void k_reset(float* __restrict__ out, int outElems) {
    int i = blockIdx.x * blockDim.x + threadIdx.x;
    int stride = gridDim.x * blockDim.x;
    int4 m1 = make_int4(-1, -1, -1, -1);
    for (int e = i; e < GRID_SZ / 4; e += stride)
        reinterpret_cast<int4*>(g_grid)[e] = m1;
    float4 z4 = make_float4(0.f, 0.f, 0.f, 0.f);
    for (int e = i; e < outElems / 4; e += stride)
        reinterpret_cast<float4*>(out)[e] = z4;
    if (blockIdx.x == 0 && threadIdx.x < 2 * CIN)
        g_stats[threadIdx.x] = 0.f;
}

// -------- kernel 2: scatter site rows into the grid, pack coords ------------
__global__ void k_scatter(const int* __restrict__ coords, int Nv) {
    int i = blockIdx.x * blockDim.x + threadIdx.x;
    if (i < Nv) {
        int4 c = reinterpret_cast<const int4*>(coords)[i];  // b, z, y, x
        int fl = (((c.x * DD + c.y) * HH + c.z) * WW) + c.w;
        g_grid[fl] = i;
        g_flat[i] = fl;
    }
}

// -------- kernel 3: per-channel sum / sumsq ---------------------------------
__global__ void k_stats(const float* __restrict__ x, int Nv) {
    __shared__ float ss[8][33];
    __shared__ float ss2[8][33];
    int tid = threadIdx.x;
    int c = tid & 31;
    int wid = tid >> 5;
    float s = 0.f, s2 = 0.f;
    int total = Nv * CIN;
    int stride = gridDim.x * blockDim.x;  // multiple of 32 -> channel fixed
    for (int e = blockIdx.x * blockDim.x + tid; e < total; e += stride) {
        float v = x[e];
        s += v;
        s2 += v * v;
    }
    ss[wid][c] = s;
    ss2[wid][c] = s2;
    __syncthreads();
    if (tid < 32) {
        float a = 0.f, b = 0.f;
#pragma unroll
        for (int k = 0; k < 8; k++) { a += ss[k][tid]; b += ss2[k][tid]; }
        atomicAdd(&g_stats[tid], a);
        atomicAdd(&g_stats[32 + tid], b);
    }
}

// -------- kernel 4: fold BN into per-channel scale/bias ---------------------
__global__ void k_finalize(const float* __restrict__ gamma,
                           const float* __restrict__ beta, int Nv) {
    int c = threadIdx.x;
    if (c < CIN) {
        float invN = 1.0f / (float)Nv;
        float mean = g_stats[c] * invN;
        float var = g_stats[32 + c] * invN - mean * mean;
        float sc = gamma[c] * rsqrtf(var + EPSV);
        g_scale[c] = sc;
        g_bias[c] = beta[c] - mean * sc;
    }
}

// -------- kernel 5: y = relu(x*scale + bias) --------------------------------
__global__ void k_norm(const float* __restrict__ x, int Nv) {
    int e = blockIdx.x * blockDim.x + threadIdx.x;  // float4 units
    int total = Nv * (CIN / 4);
    if (e < total) {
        float4 v = reinterpret_cast<const float4*>(x)[e];
        int c0 = (e * 4) & 31;
        float4 r;
        r.x = fmaxf(fmaf(v.x, g_scale[c0 + 0], g_bias[c0 + 0]), 0.f);
        r.y = fmaxf(fmaf(v.y, g_scale[c0 + 1], g_bias[c0 + 1]), 0.f);
        r.z = fmaxf(fmaf(v.z, g_scale[c0 + 2], g_bias[c0 + 2]), 0.f);
        r.w = fmaxf(fmaf(v.w, g_scale[c0 + 3], g_bias[c0 + 3]), 0.f);
        reinterpret_cast<float4*>(g_feat)[e] = r;
    }
}

// -------- kernel 6: sparse conv, one offset per blockIdx.y ------------------
// Weight column (packed f32x2) in registers, loaded ONCE per block and reused
// across 8 site-iterations. Valid pairs batched 4 at a time: 4 independent
// packed-FMA GEMV chains, smem transpose (double-buffered, 1 syncwarp/iter),
// one red.global.add.v4.f32 per 4 pairs instead of 4 scalar warp-REDs.
__global__ void __launch_bounds__(256) k_conv(const float* __restrict__ weight,
                                              float* __restrict__ out, int Nv) {
    const int o = blockIdx.y;
    const int dz = o / 25 - 2;
    const int dy = (o / 5) % 5 - 2;
    const int dx = o % 5 - 2;
    const int lane = threadIdx.x & 31;
    const int wid = threadIdx.x >> 5;

    __shared__ __align__(16) float tile[2][8][4][32];

    // Packed weight column: w2[t] = (W[2t][lane], W[2t+1][lane])
    unsigned long long w2[16];
    {
        const float* wp = weight + o * (CIN * COUT) + lane;
#pragma unroll
        for (int t = 0; t < 16; t++) {
            float a = __ldg(wp + (2 * t) * COUT);
            float b = __ldg(wp + (2 * t + 1) * COUT);
            asm("mov.b64 %0, {%1, %2};" : "=l"(w2[t]) : "f"(a), "f"(b));
        }
    }

    const int p  = lane >> 3;        // which of the 4 batched pairs this lane stores
    const int c4 = (lane & 7) * 4;   // cout base for the vector RED
    int buf = 0;

    const int blockBase = blockIdx.x * SITES_PER_BLOCK;
#pragma unroll 1
    for (int it = 0; it < SITES_PER_BLOCK / 256; it++) {
        const int base = blockBase + it * 256 + (threadIdx.x & ~31);
        const int site = base + lane;
        int nidx = -1;
        if (site < Nv) {
            int fl = g_flat[site];
            int z = (fl >> 14) & 127, y = (fl >> 7) & 127, x = fl & 127;
            if (((unsigned)(z + dz) < 128u) & ((unsigned)(y + dy) < 128u) &
                ((unsigned)(x + dx) < 128u)) {
                nidx = g_grid[fl + dz * (HH * WW) + dy * WW + dx];
            }
        }
        unsigned mask = __ballot_sync(FULLMASK, nidx >= 0);
        while (mask) {
            // Extract up to 4 valid lanes (mask is warp-uniform -> js uniform).
            int js0 = 0, js1 = 0, js2 = 0, js3 = 0, cnt = 0;
            if (mask) { js0 = __ffs(mask) - 1; mask &= mask - 1; cnt = 1; }
            if (mask) { js1 = __ffs(mask) - 1; mask &= mask - 1; cnt = 2; }
            if (mask) { js2 = __ffs(mask) - 1; mask &= mask - 1; cnt = 3; }
            if (mask) { js3 = __ffs(mask) - 1; mask &= mask - 1; cnt = 4; }

            int n0 = __shfl_sync(FULLMASK, nidx, js0);
            int n1 = __shfl_sync(FULLMASK, nidx, js1);
            int n2 = __shfl_sync(FULLMASK, nidx, js2);
            int n3 = __shfl_sync(FULLMASK, nidx, js3);
            if (cnt < 2) n1 = n0;
            if (cnt < 3) n2 = n0;
            if (cnt < 4) n3 = n0;

            const ulonglong2* f0 = reinterpret_cast<const ulonglong2*>(g_feat + (size_t)n0 * CIN);
            const ulonglong2* f1 = reinterpret_cast<const ulonglong2*>(g_feat + (size_t)n1 * CIN);
            const ulonglong2* f2 = reinterpret_cast<const ulonglong2*>(g_feat + (size_t)n2 * CIN);
            const ulonglong2* f3 = reinterpret_cast<const ulonglong2*>(g_feat + (size_t)n3 * CIN);

            unsigned long long a0 = 0ull, a1 = 0ull, a2 = 0ull, a3 = 0ull;
#pragma unroll
            for (int t = 0; t < 8; t++) {
                ulonglong2 q0 = f0[t], q1 = f1[t], q2 = f2[t], q3 = f3[t];
                FFMA2(a0, q0.x, w2[2 * t]); FFMA2(a0, q0.y, w2[2 * t + 1]);
                FFMA2(a1, q1.x, w2[2 * t]); FFMA2(a1, q1.y, w2[2 * t + 1]);
                FFMA2(a2, q2.x, w2[2 * t]); FFMA2(a2, q2.y, w2[2 * t + 1]);
                FFMA2(a3, q3.x, w2[2 * t]); FFMA2(a3, q3.y, w2[2 * t + 1]);
            }
            float r0, r1, r2, r3;
            {
                float lo, hi;
                asm("mov.b64 {%0, %1}, %2;" : "=f"(lo), "=f"(hi) : "l"(a0)); r0 = lo + hi;
                asm("mov.b64 {%0, %1}, %2;" : "=f"(lo), "=f"(hi) : "l"(a1)); r1 = lo + hi;
                asm("mov.b64 {%0, %1}, %2;" : "=f"(lo), "=f"(hi) : "l"(a2)); r2 = lo + hi;
                asm("mov.b64 {%0, %1}, %2;" : "=f"(lo), "=f"(hi) : "l"(a3)); r3 = lo + hi;
            }
            if (cnt < 2) r1 = 0.f;
            if (cnt < 3) r2 = 0.f;
            if (cnt < 4) r3 = 0.f;

            // Transpose through smem: [pair][cout] tile, conflict-free.
            tile[buf][wid][0][lane] = r0;
            tile[buf][wid][1][lane] = r1;
            tile[buf][wid][2][lane] = r2;
            tile[buf][wid][3][lane] = r3;
            __syncwarp(FULLMASK);
            float4 v = *reinterpret_cast<const float4*>(&tile[buf][wid][p][c4]);
            if (p < cnt) {
                int jp = (p == 0) ? js0 : (p == 1) ? js1 : (p == 2) ? js2 : js3;
                float* dst = out + (size_t)(base + jp) * COUT + c4;
                asm volatile("red.global.add.v4.f32 [%0], {%1, %2, %3, %4};"
                             :: "l"(dst), "f"(v.x), "f"(v.y), "f"(v.z), "f"(v.w)
                             : "memory");
            }
            buf ^= 1;   // double buffer: next STS goes to the other tile
        }
    }
}

// -------- launch ------------------------------------------------------------
extern "C" void kernel_launch(void* const* d_in, const int* in_sizes, int n_in,
                              void* d_out, int out_size) {
    const float* feats  = (const float*)d_in[0];   // [N, 32]
    const int*   coords = (const int*)d_in[1];     // [N, 4]
    const float* gamma  = (const float*)d_in[2];   // [32]
    const float* beta   = (const float*)d_in[3];   // [32]
    const float* weight = (const float*)d_in[4];   // [125, 32, 32]
    float* out = (float*)d_out;                    // [N, 32]

    int Nv = in_sizes[0] / CIN;
    if (Nv > NMAX) Nv = NMAX;

    k_reset<<<4096, 256>>>(out, Nv * CIN);
    k_scatter<<<(Nv + 255) / 256, 256>>>(coords, Nv);
    k_stats<<<1024, 256>>>(feats, Nv);
    k_finalize<<<1, 32>>>(gamma, beta, Nv);
    k_norm<<<(Nv * (CIN / 4) + 255) / 256, 256>>>(feats, Nv);

    dim3 gc((Nv + SITES_PER_BLOCK - 1) / SITES_PER_BLOCK, KVOL);
    k_conv<<<gc, 256>>>(weight, out, Nv);
}